// round 3
// baseline (speedup 1.0000x reference)
#include <cuda_runtime.h>

// Problem constants
#define H    8
#define M    1024
#define D    64
#define B    8
#define L    2048
#define NTOK 16384     // B*L tokens per head
#define TOK  128       // tokens per block
#define CHUNK 128      // codes per smem chunk

// d_out packing (float32): z_q | vq_loss | indices | new_codebooks
#define ZQ_OFF   ((size_t)0)
#define LOSS_OFF ((size_t)8388608)
#define IDX_OFF  ((size_t)8388609)
#define CB_OFF   ((size_t)8519681)

typedef unsigned long long u64;

// Scratch (no allocations allowed -> __device__ globals). Zero at module load;
// re-zeroed at the TAIL of every kernel_launch so each call sees clean state.
__device__ float g_sums[H * M * D];
__device__ float g_counts[H * M];
__device__ float g_loss;

// ---------------------------------------------------------------------------
// packed f32x2 helpers (Blackwell FFMA2 path, only reachable via PTX)
// ---------------------------------------------------------------------------
__device__ __forceinline__ u64 ffma2(u64 a, u64 b, u64 c) {
    u64 d;
    asm("fma.rn.f32x2 %0, %1, %2, %3;" : "=l"(d) : "l"(a), "l"(b), "l"(c));
    return d;
}
__device__ __forceinline__ u64 pack2(float lo, float hi) {
    u64 r;
    asm("mov.b64 %0, {%1, %2};" : "=l"(r) : "f"(lo), "f"(hi));
    return r;
}
__device__ __forceinline__ float2 unpack2(u64 v) {
    float lo, hi;
    asm("mov.b64 {%0, %1}, %2;" : "=f"(lo), "=f"(hi) : "l"(v));
    return make_float2(lo, hi);
}

// ---------------------------------------------------------------------------
struct Smem {
    float zs[D][TOK];      // z tile, k-major: 32 KB (conflict-free)
    float cs[D][CHUNK];    // codebook chunk, k-major, column-PERMUTED: 32 KB
                           // code c of a chunk lives at column (c>>2 & 1)*64 + (c>>3)*4 + (c&3)
    float pb[2][16][8];    // per-(tx-half, ty, t) partial argmax value
    int   pi[2][16][8];    // and index
    int   sidx[TOK];
    float red[8];
};

// ---------------------------------------------------------------------------
__global__ void zero_kernel() {
    int i = blockIdx.x * 256 + threadIdx.x;
    if (i < H * M * D) g_sums[i] = 0.0f;
    if (i < H * M)     g_counts[i] = 0.0f;
    if (i == 0)        g_loss = 0.0f;
}

// ---------------------------------------------------------------------------
// Main kernel: register-blocked sim GEMM + argmax + fused epilogue.
// Block: 128 tokens x 1024 codes (8 chunks of 128). Thread: 8 tokens x 8 codes.
// Warp footprint: 8 tx-groups x 4 ty-groups -> 384B unique smem traffic per
// warp-k, conflict-free -> FMA-pipe bound.
// ---------------------------------------------------------------------------
__global__ __launch_bounds__(256, 2)
void vq_main(const float* __restrict__ z, const float* __restrict__ cb,
             float* __restrict__ out) {
    extern __shared__ char smem_raw[];
    Smem& s = *reinterpret_cast<Smem*>(smem_raw);

    const int tid  = threadIdx.x;
    const int wid  = tid >> 5;
    const int lane = tid & 31;
    const int h    = blockIdx.y;
    const int n0   = blockIdx.x * TOK;
    const int b    = n0 >> 11;          // n0 / L
    const int l0   = n0 & (L - 1);      // n0 % L (multiple of 128 -> aligned)

    // Square warp footprint: 8 distinct tx x 4 distinct ty per warp.
    const int tx = (lane & 7) | ((wid & 1) << 3);   // 0..15, 8 per warp
    const int ty = (lane >> 3) | ((wid >> 1) << 2); // 0..15, 4 per warp

    // ---- load z tile [64 k x 128 tok], coalesced float4 ----
    const size_t zbase = ((size_t)(b * 512 + h * 64)) * (size_t)L + (size_t)l0;
#pragma unroll
    for (int r = 0; r < 8; r++) {
        int f  = tid + 256 * r;         // float4 id, 2048 total
        int k  = f >> 5;
        int t4 = f & 31;
        float4 v = *(const float4*)(z + zbase + (size_t)k * L + (size_t)t4 * 4);
        *(float4*)&s.zs[k][t4 * 4] = v;
    }

    float best[8];
    int   bidx[8];
#pragma unroll
    for (int t = 0; t < 8; t++) { best[t] = -3.4e38f; bidx[t] = 0; }

    const float* cbh = cb + (size_t)h * M * D;

    for (int cc = 0; cc < M / CHUNK; cc++) {
        __syncthreads();   // protect cs from previous chunk's readers (covers zs load too)
        // ---- load codebook chunk transposed + column-permuted into cs[k][pcol] ----
        {
            int m    = tid & 127;                  // code row within chunk
            int kh   = tid >> 7;                   // k-half
            int pcol = (((m >> 2) & 1) << 6) | ((m >> 3) << 2) | (m & 3);
            const float* src = cbh + (size_t)(cc * CHUNK + m) * D + kh * 32;
#pragma unroll
            for (int q = 0; q < 8; q++) {
                float4 v = *(const float4*)(src + q * 4);
                int k0 = kh * 32 + q * 4;
                s.cs[k0 + 0][pcol] = v.x;
                s.cs[k0 + 1][pcol] = v.y;
                s.cs[k0 + 2][pcol] = v.z;
                s.cs[k0 + 3][pcol] = v.w;
            }
        }
        __syncthreads();

        u64 acc[8][4];
#pragma unroll
        for (int t = 0; t < 8; t++)
#pragma unroll
            for (int j = 0; j < 4; j++) acc[t][j] = 0ull;

#pragma unroll 4
        for (int k = 0; k < D; k++) {
            float4 za = *(const float4*)&s.zs[k][ty * 8];
            float4 zb = *(const float4*)&s.zs[k][ty * 8 + 4];
            // codes tx*8+0..3 at column tx*4, codes tx*8+4..7 at column 64+tx*4
            ulonglong2 cA = *(const ulonglong2*)&s.cs[k][tx * 4];
            ulonglong2 cB = *(const ulonglong2*)&s.cs[k][64 + tx * 4];
            const u64 cp0 = cA.x, cp1 = cA.y, cp2 = cB.x, cp3 = cB.y;
            float zv[8] = {za.x, za.y, za.z, za.w, zb.x, zb.y, zb.z, zb.w};
#pragma unroll
            for (int t = 0; t < 8; t++) {
                u64 zd = pack2(zv[t], zv[t]);
                acc[t][0] = ffma2(zd, cp0, acc[t][0]);
                acc[t][1] = ffma2(zd, cp1, acc[t][1]);
                acc[t][2] = ffma2(zd, cp2, acc[t][2]);
                acc[t][3] = ffma2(zd, cp3, acc[t][3]);
            }
        }

        const int mbase = cc * CHUNK + tx * 8;
#pragma unroll
        for (int t = 0; t < 8; t++) {
#pragma unroll
            for (int j = 0; j < 4; j++) {
                float2 v = unpack2(acc[t][j]);
                if (v.x > best[t]) { best[t] = v.x; bidx[t] = mbase + 2 * j; }
                if (v.y > best[t]) { best[t] = v.y; bidx[t] = mbase + 2 * j + 1; }
            }
        }
    }

    // ---- argmax reduction: first over the 8 tx-lanes within the warp ----
#pragma unroll
    for (int t = 0; t < 8; t++) {
#pragma unroll
        for (int off = 1; off < 8; off <<= 1) {
            float ob = __shfl_xor_sync(0xffffffffu, best[t], off);
            int   oi = __shfl_xor_sync(0xffffffffu, bidx[t], off);
            if (ob > best[t] || (ob == best[t] && oi < bidx[t])) {
                best[t] = ob; bidx[t] = oi;
            }
        }
    }
    if ((lane & 7) == 0) {
        int half = wid & 1;
#pragma unroll
        for (int t = 0; t < 8; t++) {
            s.pb[half][ty][t] = best[t];
            s.pi[half][ty][t] = bidx[t];
        }
    }
    __syncthreads();

    // ---- combine the two tx-halves; write indices + counts ----
    if (tid < TOK) {
        int tyy = tid >> 3, t = tid & 7;
        float b0 = s.pb[0][tyy][t], b1 = s.pb[1][tyy][t];
        int   i0 = s.pi[0][tyy][t], i1 = s.pi[1][tyy][t];
        int m = (b1 > b0 || (b1 == b0 && i1 < i0)) ? i1 : i0;
        s.sidx[tid] = m;
        out[IDX_OFF + ((size_t)b * H + (size_t)h) * (size_t)L + (size_t)(l0 + tid)] = (float)m;
        atomicAdd(&g_counts[h * M + m], 1.0f);
    }
    __syncthreads();

    // ---- epilogue: z_q, loss, segment sums ----
    float lsum = 0.0f;
#pragma unroll
    for (int i = 0; i < 32; i++) {
        int e = i * 256 + tid;          // 8192 elements: (k, tok)
        int k = e >> 7;
        int t = e & 127;
        int m = s.sidx[t];
        float c  = __ldg(cbh + (size_t)m * D + k);
        float zv = s.zs[k][t];
        size_t o = ((size_t)(b * 512 + h * 64 + k)) * (size_t)L + (size_t)(l0 + t);
        out[ZQ_OFF + o] = c;
        float dd = zv - c;
        lsum += dd * dd;
        atomicAdd(&g_sums[(h * M + m) * D + k], zv);
    }

    // block-reduce loss -> one atomic per block
#pragma unroll
    for (int o = 16; o > 0; o >>= 1)
        lsum += __shfl_xor_sync(0xffffffffu, lsum, o);
    if ((tid & 31) == 0) s.red[tid >> 5] = lsum;
    __syncthreads();
    if (tid == 0) {
        float tt = 0.0f;
#pragma unroll
        for (int w = 0; w < 8; w++) tt += s.red[w];
        atomicAdd(&g_loss, tt);
    }
}

// ---------------------------------------------------------------------------
// Update kernel: slerp + rms_norm codebook EMA (1 warp per code) + vq_loss.
// ---------------------------------------------------------------------------
__global__ void vq_update(const float* __restrict__ cb, float* __restrict__ out) {
    if (blockIdx.x == 0 && threadIdx.x == 0) {
        // vq_loss = codebook_loss + 0.25*commitment_loss = 1.25 * MSE
        out[LOSS_OFF] = 1.25f * g_loss * (1.0f / 8388608.0f);
    }

    const int code = blockIdx.x * 8 + (threadIdx.x >> 5);
    const int lane = threadIdx.x & 31;
    if (code >= H * M) return;

    const float* old = cb + (size_t)code * D;
    float o0 = old[lane];
    float o1 = old[lane + 32];
    float cnt = g_counts[code];
    float r0, r1;

    if (cnt > 0.0f) {
        float m0 = g_sums[code * D + lane] / cnt;
        float m1 = g_sums[code * D + lane + 32] / cnt;

        float dot = m0 * o0 + m1 * o1;
        float nl  = m0 * m0 + m1 * m1;
        float nh  = o0 * o0 + o1 * o1;
#pragma unroll
        for (int o = 16; o > 0; o >>= 1) {
            dot += __shfl_xor_sync(0xffffffffu, dot, o);
            nl  += __shfl_xor_sync(0xffffffffu, nl,  o);
            nh  += __shfl_xor_sync(0xffffffffu, nh,  o);
        }
        float cosv = dot / fmaxf(sqrtf(nl) * sqrtf(nh), 1e-8f);
        cosv = fminf(fmaxf(cosv, (float)(-1.0 + 1e-7)), (float)(1.0 - 1e-7));
        float omega = acosf(cosv);
        float so = sinf(omega);
        float wl = sinf(0.01f * omega);   // (1 - decay) * omega
        float wh = sinf(0.99f * omega);   // decay * omega
        r0 = (m0 * wl + o0 * wh) / so;
        r1 = (m1 * wl + o1 * wh) / so;

        float ss = r0 * r0 + r1 * r1;
#pragma unroll
        for (int o = 16; o > 0; o >>= 1)
            ss += __shfl_xor_sync(0xffffffffu, ss, o);
        float inv = 1.0f / sqrtf(ss * (1.0f / 64.0f) + 1.1920929e-07f);
        r0 *= inv;
        r1 *= inv;
    } else {
        r0 = o0;
        r1 = o1;
    }

    out[CB_OFF + (size_t)code * D + lane]      = r0;
    out[CB_OFF + (size_t)code * D + lane + 32] = r1;
}

// ---------------------------------------------------------------------------
extern "C" void kernel_launch(void* const* d_in, const int* in_sizes, int n_in,
                              void* d_out, int out_size) {
    const float* z  = (const float*)d_in[0];   // [8, 512, 2048]
    const float* cb = (const float*)d_in[1];   // [8, 1024, 64]
    float* out = (float*)d_out;

    cudaFuncSetAttribute(vq_main, cudaFuncAttributeMaxDynamicSharedMemorySize,
                         (int)sizeof(Smem));

    dim3 grid(NTOK / TOK, H);
    vq_main<<<grid, 256, sizeof(Smem)>>>(z, cb, out);

    vq_update<<<H * M / 8, 256>>>(cb, out);

    // Reset scratch for the NEXT invocation (initial state is zero at load).
    zero_kernel<<<(H * M * D + 255) / 256, 256>>>();
}